// round 6
// baseline (speedup 1.0000x reference)
#include <cuda_runtime.h>
#include <cuda_bf16.h>
#include <math.h>
#include <stdint.h>

#define BSZ 256
#define DIM 4096
#define TMAX 19
#define NTHREADS 256
#define KCAP 20

// ------------- scratch (__device__ globals; aligned, no allocations) -------------
__device__ __align__(128) __nv_bfloat16 g_wsplit[3ull * DIM * DIM]; // 96MB: W = w1+w2+w3 exactly
__device__ __align__(128) __nv_bfloat16 g_abf16[BSZ * DIM];         // x as bf16 (exact, binary)
__device__ __align__(128) float g_gradx[BSZ * DIM];
__device__ __align__(128) float g_l0[BSZ * DIM];                    // initial logits l0
__device__ __align__(128) float g_topv[BSZ * TMAX * KCAP];
__device__ __align__(128) int   g_topi[BSZ * TMAX * KCAP];
__device__ __align__(128) float g_S0[BSZ];
__device__ __align__(128) float g_score[BSZ];
__device__ __align__(128) int   g_idxbuf[BSZ * TMAX];
__device__ __align__(128) float g_logfwd[BSZ];
__device__ __align__(128) int   g_flipidx[BSZ * TMAX];
__device__ __align__(128) int   g_nf[BSZ];

// ======================= helpers =======================
__device__ __forceinline__ uint32_t smem_u32(const void* p) {
    uint32_t a;
    asm("{ .reg .u64 t; cvta.to.shared.u64 t, %1; cvt.u32.u64 %0, t; }" : "=r"(a) : "l"(p));
    return a;
}
__device__ __forceinline__ void cpasync16(uint32_t dst, const void* src) {
    asm volatile("cp.async.cg.shared.global [%0], [%1], 16;" :: "r"(dst), "l"(src) : "memory");
}
#define CP_COMMIT() asm volatile("cp.async.commit_group;" ::: "memory")
#define CP_WAIT2()  asm volatile("cp.async.wait_group 2;" ::: "memory")

__device__ __forceinline__ void ldsm_x4(uint32_t& r0, uint32_t& r1, uint32_t& r2, uint32_t& r3,
                                        uint32_t addr) {
    asm volatile("ldmatrix.sync.aligned.m8n8.x4.shared.b16 {%0,%1,%2,%3}, [%4];"
                 : "=r"(r0), "=r"(r1), "=r"(r2), "=r"(r3) : "r"(addr));
}
__device__ __forceinline__ void mma16816(float& c0, float& c1, float& c2, float& c3,
                                         uint32_t a0, uint32_t a1, uint32_t a2, uint32_t a3,
                                         uint32_t b0, uint32_t b1) {
    asm volatile("mma.sync.aligned.m16n8k16.row.col.f32.bf16.bf16.f32 "
                 "{%0,%1,%2,%3}, {%4,%5,%6,%7}, {%8,%9}, {%0,%1,%2,%3};"
                 : "+f"(c0), "+f"(c1), "+f"(c2), "+f"(c3)
                 : "r"(a0), "r"(a1), "r"(a2), "r"(a3), "r"(b0), "r"(b1));
}

// ====================== split W into 3 exact bf16 terms ======================
__global__ __launch_bounds__(256) void split_w_kernel(const float* __restrict__ W) {
    size_t i4 = ((size_t)blockIdx.x * 256 + threadIdx.x);
    float4 w = ((const float4*)W)[i4];
    float v[4] = {w.x, w.y, w.z, w.w};
    size_t base = i4 * 4;
    #pragma unroll
    for (int s = 0; s < 3; s++) {
        __nv_bfloat16 h0 = __float2bfloat16_rn(v[0]); v[0] -= __bfloat162float(h0);
        __nv_bfloat16 h1 = __float2bfloat16_rn(v[1]); v[1] -= __bfloat162float(h1);
        __nv_bfloat16 h2 = __float2bfloat16_rn(v[2]); v[2] -= __bfloat162float(h2);
        __nv_bfloat16 h3 = __float2bfloat16_rn(v[3]); v[3] -= __bfloat162float(h3);
        __nv_bfloat162* d2 = (__nv_bfloat162*)(g_wsplit + (size_t)s * DIM * DIM + base);
        d2[0] = __nv_bfloat162(h0, h1);
        d2[1] = __nv_bfloat162(h2, h3);
    }
}

__global__ __launch_bounds__(256) void conv_x_kernel(const float* __restrict__ x) {
    size_t i4 = ((size_t)blockIdx.x * 256 + threadIdx.x);
    float4 w = ((const float4*)x)[i4];
    __nv_bfloat162* d2 = (__nv_bfloat162*)(g_abf16 + i4 * 4);
    d2[0] = __nv_bfloat162(__float2bfloat16_rn(w.x), __float2bfloat16_rn(w.y));
    d2[1] = __nv_bfloat162(__float2bfloat16_rn(w.z), __float2bfloat16_rn(w.w));
}

// ============== GEMM via mma.sync (HMMA): gradx = x@W + b ==============
#define BM 64
#define BN 128
#define BKE 64
#define NIT (3 * DIM / BKE)    // 192
#define STAGE_BYTES (BM * 128 + BN * 128)
#define SMEM_TOTAL (4 * STAGE_BYTES)

__device__ __forceinline__ void load_stage(uint32_t sbase, int it, int buf, int bm, int bn, int tid) {
    int kk0 = it * BKE;
    int sp = kk0 >> 12;
    int ki = kk0 & (DIM - 1);
    const __nv_bfloat16* Ab = g_abf16 + (size_t)bm * DIM + ki;
    const __nv_bfloat16* Bb = g_wsplit + (size_t)sp * DIM * DIM + (size_t)bn * DIM + ki;
    uint32_t abuf = sbase + buf * STAGE_BYTES;
    uint32_t bbuf = abuf + BM * 128;
    #pragma unroll
    for (int i = 0; i < 2; i++) {
        int c = tid + i * 256;
        int row = c >> 3, ch = c & 7;
        uint32_t off = row * 128 + ((ch * 16) ^ ((row & 7) * 16));
        cpasync16(abuf + off, Ab + (size_t)row * DIM + ch * 8);
    }
    #pragma unroll
    for (int i = 0; i < 4; i++) {
        int c = tid + i * 256;
        int row = c >> 3, ch = c & 7;
        uint32_t off = row * 128 + ((ch * 16) ^ ((row & 7) * 16));
        cpasync16(bbuf + off, Bb + (size_t)row * DIM + ch * 8);
    }
    CP_COMMIT();
}

__global__ __launch_bounds__(256) void gemm_mma(const float* __restrict__ bias) {
    extern __shared__ __align__(128) char dsm[];
    uint32_t sbase = smem_u32(dsm);
    int tid = threadIdx.x;
    int wid = tid >> 5, lane = tid & 31;
    int bn = blockIdx.x * BN;
    int bm = blockIdx.y * BM;

    int wm = (wid >> 2) * 32;
    int wn = (wid & 3) * 32;

    int tile = lane >> 3, rl = lane & 7;
    int a_row_off = (tile & 1) * 8 + rl;
    int a_kh = (tile >> 1) * 16;
    int b_n_off = (tile >> 1) * 8 + rl;
    int b_kh = (tile & 1) * 16;

    int arow0 = wm + a_row_off;
    int arow1 = arow0 + 16;
    uint32_t a_base0 = arow0 * 128, a_rm0 = (arow0 & 7) * 16;
    uint32_t a_base1 = arow1 * 128, a_rm1 = (arow1 & 7) * 16;
    int bnr0 = wn + b_n_off;
    int bnr1 = bnr0 + 16;
    uint32_t b_base0 = bnr0 * 128, b_rm0 = (bnr0 & 7) * 16;
    uint32_t b_base1 = bnr1 * 128, b_rm1 = (bnr1 & 7) * 16;

    float c[2][4][4];
    #pragma unroll
    for (int i = 0; i < 2; i++)
        #pragma unroll
        for (int j = 0; j < 4; j++)
            #pragma unroll
            for (int k = 0; k < 4; k++) c[i][j][k] = 0.f;

    load_stage(sbase, 0, 0, bm, bn, tid);
    load_stage(sbase, 1, 1, bm, bn, tid);
    load_stage(sbase, 2, 2, bm, bn, tid);

    for (int it = 0; it < NIT; ++it) {
        CP_WAIT2();
        __syncthreads();
        int buf = it & 3;
        uint32_t Asm = sbase + buf * STAGE_BYTES;
        uint32_t Bsm = Asm + BM * 128;
        #pragma unroll
        for (int ks = 0; ks < 4; ks++) {
            uint32_t kb = ks * 32;
            uint32_t a0[4], a1[4], b0[4], b1[4];
            ldsm_x4(a0[0], a0[1], a0[2], a0[3], Asm + a_base0 + ((kb + a_kh) ^ a_rm0));
            ldsm_x4(a1[0], a1[1], a1[2], a1[3], Asm + a_base1 + ((kb + a_kh) ^ a_rm1));
            ldsm_x4(b0[0], b0[1], b0[2], b0[3], Bsm + b_base0 + ((kb + b_kh) ^ b_rm0));
            ldsm_x4(b1[0], b1[1], b1[2], b1[3], Bsm + b_base1 + ((kb + b_kh) ^ b_rm1));
            #pragma unroll
            for (int fi = 0; fi < 2; fi++) {
                uint32_t* a = fi ? a1 : a0;
                mma16816(c[fi][0][0], c[fi][0][1], c[fi][0][2], c[fi][0][3],
                         a[0], a[1], a[2], a[3], b0[0], b0[1]);
                mma16816(c[fi][1][0], c[fi][1][1], c[fi][1][2], c[fi][1][3],
                         a[0], a[1], a[2], a[3], b0[2], b0[3]);
                mma16816(c[fi][2][0], c[fi][2][1], c[fi][2][2], c[fi][2][3],
                         a[0], a[1], a[2], a[3], b1[0], b1[1]);
                mma16816(c[fi][3][0], c[fi][3][1], c[fi][3][2], c[fi][3][3],
                         a[0], a[1], a[2], a[3], b1[2], b1[3]);
            }
        }
        __syncthreads();
        if (it + 3 < NIT) load_stage(sbase, it + 3, (it + 3) & 3, bm, bn, tid);
    }

    int rbase = bm + wm + (lane >> 2);
    int cbase = bn + wn + 2 * (lane & 3);
    #pragma unroll
    for (int fi = 0; fi < 2; fi++) {
        #pragma unroll
        for (int bj = 0; bj < 4; bj++) {
            int col = cbase + bj * 8;
            float bx = bias[col], by = bias[col + 1];
            int r0 = rbase + fi * 16;
            float2 v0 = {c[fi][bj][0] + bx, c[fi][bj][1] + by};
            float2 v1 = {c[fi][bj][2] + bx, c[fi][bj][3] + by};
            *(float2*)&g_gradx[(size_t)r0 * DIM + col] = v0;
            *(float2*)&g_gradx[(size_t)(r0 + 8) * DIM + col] = v1;
        }
    }
}

// ================ Gumbel: -log(-log u), fast-math-safe =================
__device__ __forceinline__ float gumbel_from_u(float u) {
    float nl = (u > 0.75f) ? (-log1pf(u - 1.0f)) : (-logf(u));
    return -logf(nl);
}

// ============ prep: l0 = (1-2x)*grad/2, S0 = sum exp(l0), score_x ============
__global__ __launch_bounds__(256) void prep_l0(
    const float* __restrict__ x, const float* __restrict__ bias)
{
    __shared__ float rsum[8], rsum2[8];
    int b = blockIdx.x;
    int tid = threadIdx.x, lane = tid & 31, wid = tid >> 5;
    const float* gx = g_gradx + (size_t)b * DIM;
    const float* xr = x + (size_t)b * DIM;
    float* l0 = g_l0 + (size_t)b * DIM;

    float s_part = 0.f, sc_part = 0.f;
    for (int j = tid; j < DIM; j += NTHREADS) {
        float g  = gx[j];
        float xv = xr[j];
        float l  = (1.f - 2.f * xv) * (0.5f * g);
        l0[j] = l;
        s_part  += expf(l);
        sc_part += xv * 0.5f * (g + bias[j]);
    }
    #pragma unroll
    for (int o = 16; o; o >>= 1) {
        s_part  += __shfl_down_sync(0xffffffffu, s_part, o);
        sc_part += __shfl_down_sync(0xffffffffu, sc_part, o);
    }
    if (lane == 0) { rsum[wid] = s_part; rsum2[wid] = sc_part; }
    __syncthreads();
    if (tid == 0) {
        float S = 0.f, sc = 0.f;
        #pragma unroll
        for (int w = 0; w < 8; w++) { S += rsum[w]; sc += rsum2[w]; }
        g_S0[b] = S; g_score[b] = sc;
    }
}

// ====== parallel top-(t+1): keys = l0 + gumbel(u_t), per (b,t) independent ======
__global__ __launch_bounds__(256) void topk_kernel(
    const float* __restrict__ unif, const int* __restrict__ radius)
{
    int t = blockIdx.x, b = blockIdx.y;
    if (t >= radius[b]) return;

    __shared__ __align__(16) float keys[DIM];
    __shared__ float rf[8];
    __shared__ int   ri[8];

    int tid = threadIdx.x, lane = tid & 31, wid = tid >> 5;
    const float* up = unif + ((size_t)t * BSZ + b) * DIM;
    const float* l0 = g_l0 + (size_t)b * DIM;

    #pragma unroll
    for (int i = 0; i < DIM / NTHREADS; i++) {
        int j = tid + i * NTHREADS;
        keys[j] = l0[j] + gumbel_from_u(up[j]);
    }
    __syncthreads();

    int K = t + 1;
    float* outv = g_topv + ((size_t)b * TMAX + t) * KCAP;
    int*   outi = g_topi + ((size_t)b * TMAX + t) * KCAP;

    for (int k = 0; k < K; k++) {
        float best = -3.0e38f; int bi = 0;
        #pragma unroll
        for (int i = 0; i < DIM / NTHREADS; i++) {
            int j = tid + i * NTHREADS;
            float v = keys[j];
            if (v > best) { best = v; bi = j; }       // ascending j -> lowest idx on tie
        }
        #pragma unroll
        for (int o = 16; o; o >>= 1) {
            float ov = __shfl_down_sync(0xffffffffu, best, o);
            int   oi = __shfl_down_sync(0xffffffffu, bi, o);
            if (ov > best || (ov == best && oi < bi)) { best = ov; bi = oi; }
        }
        if (lane == 0) { rf[wid] = best; ri[wid] = bi; }
        __syncthreads();
        if (tid == 0) {
            float bv = rf[0]; int bbi = ri[0];
            #pragma unroll
            for (int w = 1; w < 8; w++)
                if (rf[w] > bv || (rf[w] == bv && ri[w] < bbi)) { bv = rf[w]; bbi = ri[w]; }
            outv[k] = bv; outi[k] = bbi;
            keys[bbi] = -3.0e38f;
        }
        __syncthreads();
    }
}

// ============ tiny sequential phase: one thread per batch row ============
__global__ void seq_kernel(const float* __restrict__ unif,
                           const int* __restrict__ radius)
{
    int b = blockIdx.x * blockDim.x + threadIdx.x;
    if (b >= BSZ) return;

    const float* l0 = g_l0 + (size_t)b * DIM;
    int r = radius[b];
    float S = g_S0[b];
    float sum_sel = 0.f;
    int fi[TMAX + 1];
    int nf = 0;

    for (int t = 0; t < r; t++) {
        const float* tv = g_topv + ((size_t)b * TMAX + t) * KCAP;
        const int*   ti = g_topi + ((size_t)b * TMAX + t) * KCAP;
        // first top-list entry not in flip set (= max over unflipped indices)
        float candv = -3.0e38f; int candi = 0;
        for (int k = 0; k <= t; k++) {
            int idx = ti[k];
            bool inF = false;
            for (int f = 0; f < nf; f++) if (fi[f] == idx) { inF = true; break; }
            if (!inF) { candv = tv[k]; candi = idx; break; }
        }
        // corrected keys for flipped indices: -l0 + gumbel
        float corrv = -3.0e38f; int corri = 0x7fffffff;
        for (int f = 0; f < nf; f++) {
            int i = fi[f];
            float u = unif[((size_t)t * BSZ + b) * DIM + i];
            float key = -l0[i] + gumbel_from_u(u);
            if (key > corrv || (key == corrv && i < corri)) { corrv = key; corri = i; }
        }
        int istar; float lcur;
        if (corrv > candv || (corrv == candv && corri < candi)) {
            istar = corri; lcur = -l0[istar];
        } else {
            istar = candi; lcur = l0[istar];
        }
        sum_sel += lcur - logf(S);
        S += expf(-lcur) - expf(lcur);
        // toggle membership
        int found = -1;
        for (int f = 0; f < nf; f++) if (fi[f] == istar) { found = f; break; }
        if (found >= 0) { fi[found] = fi[nf - 1]; nf--; }
        else            { fi[nf++] = istar; }
        g_idxbuf[b * TMAX + t] = istar;
    }
    g_logfwd[b] = sum_sel + g_score[b];

    // sort flip set ascending (deterministic downstream accumulation)
    for (int a = 1; a < nf; a++) {
        int v = fi[a]; int c = a;
        while (c > 0 && fi[c - 1] > v) { fi[c] = fi[c - 1]; c--; }
        fi[c] = v;
    }
    g_nf[b] = nf;
    for (int f = 0; f < nf; f++) g_flipidx[b * TMAX + f] = fi[f];
}

// ============ fused: sparse grad_y + backward + accept + output ============
// grad_y = grad_x + sum_{i in F} (1-2x_i) * W[i,:]
__global__ __launch_bounds__(256) void bwd_fused(
    const float* __restrict__ x, const float* __restrict__ W,
    const float* __restrict__ bias, const float* __restrict__ uacc,
    const int* __restrict__ radius, float* __restrict__ out)
{
    __shared__ __align__(16) float gy[DIM];   // grad_y, then reused as l_j
    __shared__ __align__(16) float yb[DIM];   // y bits
    __shared__ float rsum[8], rsum2[8];
    __shared__ int   fidx[TMAX + 1];
    __shared__ float fsgn[TMAX + 1];
    __shared__ float s_acc;

    int b = blockIdx.x;
    int tid = threadIdx.x;
    int lane = tid & 31, wid = tid >> 5;

    const float* xr  = x + (size_t)b * DIM;
    const float* gxr = g_gradx + (size_t)b * DIM;

    int n = g_nf[b];
    if (tid < n) {
        int i = g_flipidx[b * TMAX + tid];
        fidx[tid] = i;
        fsgn[tid] = 1.f - 2.f * xr[i];       // y_i - x_i
    }
    __syncthreads();

    // y = x with flips; grad_y = grad_x + sum sgn*W[fi,:]
    for (int j = tid; j < DIM; j += NTHREADS) {
        yb[j] = xr[j];
        float acc = gxr[j];
        for (int f = 0; f < n; f++)
            acc += fsgn[f] * W[(size_t)fidx[f] * DIM + j];
        gy[j] = acc;
    }
    __syncthreads();
    if (tid < n) yb[fidx[tid]] = 1.f - yb[fidx[tid]];
    __syncthreads();

    // score_y, S over delta_y; convert gy -> l_j in place
    float s_part = 0.f, sc_part = 0.f;
    for (int j = tid; j < DIM; j += NTHREADS) {
        float g  = gy[j];
        float yv = yb[j];
        float l  = (1.f - 2.f * yv) * (0.5f * g);
        s_part  += expf(l);
        sc_part += yv * 0.5f * (g + bias[j]);
        gy[j] = l;
    }
    #pragma unroll
    for (int o = 16; o; o >>= 1) {
        s_part  += __shfl_down_sync(0xffffffffu, s_part, o);
        sc_part += __shfl_down_sync(0xffffffffu, sc_part, o);
    }
    if (lane == 0) { rsum[wid] = s_part; rsum2[wid] = sc_part; }
    __syncthreads();

    if (tid == 0) {
        float S = 0.f, score = 0.f;
        #pragma unroll
        for (int w = 0; w < 8; w++) { S += rsum[w]; score += rsum2[w]; }
        int r = radius[b];
        float sum_sel = 0.f;
        for (int t = r - 1; t >= 0; t--) {
            int i = g_idxbuf[b * TMAX + t];
            float l = gy[i];
            sum_sel += l - logf(S);
            S += expf(-l) - expf(l);
            gy[i] = -l;
        }
        float log_bwd = sum_sel + score;
        float ratio = expf(log_bwd - g_logfwd[b]);
        s_acc = (ratio >= uacc[b]) ? 1.0f : 0.0f;
    }
    __syncthreads();

    float a = s_acc;
    float* orow = out + (size_t)b * DIM;
    for (int j = tid << 2; j < DIM; j += NTHREADS * 4) {
        float4 yv4 = *(const float4*)&yb[j];
        float4 xv4 = *(const float4*)(xr + j);
        float4 o;
        o.x = (a != 0.f) ? yv4.x : xv4.x;
        o.y = (a != 0.f) ? yv4.y : xv4.y;
        o.z = (a != 0.f) ? yv4.z : xv4.z;
        o.w = (a != 0.f) ? yv4.w : xv4.w;
        *(float4*)(orow + j) = o;
    }
}

// =============================== launch ================================
extern "C" void kernel_launch(void* const* d_in, const int* in_sizes, int n_in,
                              void* d_out, int out_size)
{
    const float* x      = (const float*)d_in[0];
    const float* W      = (const float*)d_in[1];
    const float* bias   = (const float*)d_in[2];
    const float* unif   = (const float*)d_in[3];
    const float* uacc   = (const float*)d_in[4];
    const int*   radius = (const int*)d_in[5];
    float* out = (float*)d_out;

    static int smem_set = 0;
    if (!smem_set) {
        cudaFuncSetAttribute(gemm_mma, cudaFuncAttributeMaxDynamicSharedMemorySize, SMEM_TOTAL);
        smem_set = 1;
    }

    split_w_kernel<<<(DIM * DIM / 4) / 256, 256>>>(W);
    conv_x_kernel<<<(BSZ * DIM / 4) / 256, 256>>>(x);
    gemm_mma<<<dim3(DIM / BN, BSZ / BM), 256, SMEM_TOTAL>>>(bias);
    prep_l0<<<BSZ, 256>>>(x, bias);
    topk_kernel<<<dim3(TMAX, BSZ), 256>>>(unif, radius);
    seq_kernel<<<32, 8>>>(unif, radius);
    bwd_fused<<<BSZ, 256>>>(x, W, bias, uacc, radius, out);
}

// round 8
// speedup vs baseline: 1.4678x; 1.4678x over previous
#include <cuda_runtime.h>
#include <cuda_bf16.h>
#include <math.h>
#include <stdint.h>

#define BSZ 256
#define DIM 4096
#define TMAX 19
#define NTHREADS 256

// ------------- scratch (__device__ globals; aligned, no allocations) -------------
__device__ __align__(128) __nv_bfloat16 g_wsplit[3ull * DIM * DIM]; // 96MB: W = w1+w2+w3 exactly
__device__ __align__(128) __nv_bfloat16 g_abf16[BSZ * DIM];         // x as bf16 (exact, binary)
__device__ __align__(128) float g_gradx[BSZ * DIM];
__device__ __align__(128) float g_t1v[BSZ * TMAX];
__device__ __align__(128) int   g_t1i[BSZ * TMAX];
__device__ __align__(128) float g_t2v[BSZ * TMAX];
__device__ __align__(128) int   g_t2i[BSZ * TMAX];
__device__ __align__(128) int   g_idxbuf[BSZ * TMAX];
__device__ __align__(128) float g_logfwd[BSZ];
__device__ __align__(128) int   g_flipidx[BSZ * TMAX];
__device__ __align__(128) int   g_nf[BSZ];

// ======================= helpers =======================
__device__ __forceinline__ uint32_t smem_u32(const void* p) {
    uint32_t a;
    asm("{ .reg .u64 t; cvta.to.shared.u64 t, %1; cvt.u32.u64 %0, t; }" : "=r"(a) : "l"(p));
    return a;
}
__device__ __forceinline__ void cpasync16(uint32_t dst, const void* src) {
    asm volatile("cp.async.cg.shared.global [%0], [%1], 16;" :: "r"(dst), "l"(src) : "memory");
}
#define CP_COMMIT() asm volatile("cp.async.commit_group;" ::: "memory")
#define CP_WAIT2()  asm volatile("cp.async.wait_group 2;" ::: "memory")

__device__ __forceinline__ void ldsm_x4(uint32_t& r0, uint32_t& r1, uint32_t& r2, uint32_t& r3,
                                        uint32_t addr) {
    asm volatile("ldmatrix.sync.aligned.m8n8.x4.shared.b16 {%0,%1,%2,%3}, [%4];"
                 : "=r"(r0), "=r"(r1), "=r"(r2), "=r"(r3) : "r"(addr));
}
__device__ __forceinline__ void mma16816(float& c0, float& c1, float& c2, float& c3,
                                         uint32_t a0, uint32_t a1, uint32_t a2, uint32_t a3,
                                         uint32_t b0, uint32_t b1) {
    asm volatile("mma.sync.aligned.m16n8k16.row.col.f32.bf16.bf16.f32 "
                 "{%0,%1,%2,%3}, {%4,%5,%6,%7}, {%8,%9}, {%0,%1,%2,%3};"
                 : "+f"(c0), "+f"(c1), "+f"(c2), "+f"(c3)
                 : "r"(a0), "r"(a1), "r"(a2), "r"(a3), "r"(b0), "r"(b1));
}

// ====================== split W into 3 exact bf16 terms ======================
__global__ __launch_bounds__(256) void split_w_kernel(const float* __restrict__ W) {
    size_t i4 = ((size_t)blockIdx.x * 256 + threadIdx.x);
    float4 w = ((const float4*)W)[i4];
    float v[4] = {w.x, w.y, w.z, w.w};
    size_t base = i4 * 4;
    #pragma unroll
    for (int s = 0; s < 3; s++) {
        __nv_bfloat16 h0 = __float2bfloat16_rn(v[0]); v[0] -= __bfloat162float(h0);
        __nv_bfloat16 h1 = __float2bfloat16_rn(v[1]); v[1] -= __bfloat162float(h1);
        __nv_bfloat16 h2 = __float2bfloat16_rn(v[2]); v[2] -= __bfloat162float(h2);
        __nv_bfloat16 h3 = __float2bfloat16_rn(v[3]); v[3] -= __bfloat162float(h3);
        __nv_bfloat162* d2 = (__nv_bfloat162*)(g_wsplit + (size_t)s * DIM * DIM + base);
        d2[0] = __nv_bfloat162(h0, h1);
        d2[1] = __nv_bfloat162(h2, h3);
    }
}

__global__ __launch_bounds__(256) void conv_x_kernel(const float* __restrict__ x) {
    size_t i4 = ((size_t)blockIdx.x * 256 + threadIdx.x);
    float4 w = ((const float4*)x)[i4];
    __nv_bfloat162* d2 = (__nv_bfloat162*)(g_abf16 + i4 * 4);
    d2[0] = __nv_bfloat162(__float2bfloat16_rn(w.x), __float2bfloat16_rn(w.y));
    d2[1] = __nv_bfloat162(__float2bfloat16_rn(w.z), __float2bfloat16_rn(w.w));
}

// ============== GEMM via mma.sync (HMMA): gradx = x@W + b ==============
#define BM 64
#define BN 128
#define BKE 64
#define NIT (3 * DIM / BKE)    // 192
#define STAGE_BYTES (BM * 128 + BN * 128)
#define SMEM_TOTAL (4 * STAGE_BYTES)

__device__ __forceinline__ void load_stage(uint32_t sbase, int it, int buf, int bm, int bn, int tid) {
    int kk0 = it * BKE;
    int sp = kk0 >> 12;
    int ki = kk0 & (DIM - 1);
    const __nv_bfloat16* Ab = g_abf16 + (size_t)bm * DIM + ki;
    const __nv_bfloat16* Bb = g_wsplit + (size_t)sp * DIM * DIM + (size_t)bn * DIM + ki;
    uint32_t abuf = sbase + buf * STAGE_BYTES;
    uint32_t bbuf = abuf + BM * 128;
    #pragma unroll
    for (int i = 0; i < 2; i++) {
        int c = tid + i * 256;
        int row = c >> 3, ch = c & 7;
        uint32_t off = row * 128 + ((ch * 16) ^ ((row & 7) * 16));
        cpasync16(abuf + off, Ab + (size_t)row * DIM + ch * 8);
    }
    #pragma unroll
    for (int i = 0; i < 4; i++) {
        int c = tid + i * 256;
        int row = c >> 3, ch = c & 7;
        uint32_t off = row * 128 + ((ch * 16) ^ ((row & 7) * 16));
        cpasync16(bbuf + off, Bb + (size_t)row * DIM + ch * 8);
    }
    CP_COMMIT();
}

__global__ __launch_bounds__(256) void gemm_mma(const float* __restrict__ bias) {
    extern __shared__ __align__(128) char dsm[];
    uint32_t sbase = smem_u32(dsm);
    int tid = threadIdx.x;
    int wid = tid >> 5, lane = tid & 31;
    int bn = blockIdx.x * BN;
    int bm = blockIdx.y * BM;

    int wm = (wid >> 2) * 32;
    int wn = (wid & 3) * 32;

    int tile = lane >> 3, rl = lane & 7;
    int a_row_off = (tile & 1) * 8 + rl;
    int a_kh = (tile >> 1) * 16;
    int b_n_off = (tile >> 1) * 8 + rl;
    int b_kh = (tile & 1) * 16;

    int arow0 = wm + a_row_off;
    int arow1 = arow0 + 16;
    uint32_t a_base0 = arow0 * 128, a_rm0 = (arow0 & 7) * 16;
    uint32_t a_base1 = arow1 * 128, a_rm1 = (arow1 & 7) * 16;
    int bnr0 = wn + b_n_off;
    int bnr1 = bnr0 + 16;
    uint32_t b_base0 = bnr0 * 128, b_rm0 = (bnr0 & 7) * 16;
    uint32_t b_base1 = bnr1 * 128, b_rm1 = (bnr1 & 7) * 16;

    float c[2][4][4];
    #pragma unroll
    for (int i = 0; i < 2; i++)
        #pragma unroll
        for (int j = 0; j < 4; j++)
            #pragma unroll
            for (int k = 0; k < 4; k++) c[i][j][k] = 0.f;

    load_stage(sbase, 0, 0, bm, bn, tid);
    load_stage(sbase, 1, 1, bm, bn, tid);
    load_stage(sbase, 2, 2, bm, bn, tid);

    for (int it = 0; it < NIT; ++it) {
        CP_WAIT2();
        __syncthreads();
        int buf = it & 3;
        uint32_t Asm = sbase + buf * STAGE_BYTES;
        uint32_t Bsm = Asm + BM * 128;
        #pragma unroll
        for (int ks = 0; ks < 4; ks++) {
            uint32_t kb = ks * 32;
            uint32_t a0[4], a1[4], b0[4], b1[4];
            ldsm_x4(a0[0], a0[1], a0[2], a0[3], Asm + a_base0 + ((kb + a_kh) ^ a_rm0));
            ldsm_x4(a1[0], a1[1], a1[2], a1[3], Asm + a_base1 + ((kb + a_kh) ^ a_rm1));
            ldsm_x4(b0[0], b0[1], b0[2], b0[3], Bsm + b_base0 + ((kb + b_kh) ^ b_rm0));
            ldsm_x4(b1[0], b1[1], b1[2], b1[3], Bsm + b_base1 + ((kb + b_kh) ^ b_rm1));
            #pragma unroll
            for (int fi = 0; fi < 2; fi++) {
                uint32_t* a = fi ? a1 : a0;
                mma16816(c[fi][0][0], c[fi][0][1], c[fi][0][2], c[fi][0][3],
                         a[0], a[1], a[2], a[3], b0[0], b0[1]);
                mma16816(c[fi][1][0], c[fi][1][1], c[fi][1][2], c[fi][1][3],
                         a[0], a[1], a[2], a[3], b0[2], b0[3]);
                mma16816(c[fi][2][0], c[fi][2][1], c[fi][2][2], c[fi][2][3],
                         a[0], a[1], a[2], a[3], b1[0], b1[1]);
                mma16816(c[fi][3][0], c[fi][3][1], c[fi][3][2], c[fi][3][3],
                         a[0], a[1], a[2], a[3], b1[2], b1[3]);
            }
        }
        __syncthreads();
        if (it + 3 < NIT) load_stage(sbase, it + 3, (it + 3) & 3, bm, bn, tid);
    }

    int rbase = bm + wm + (lane >> 2);
    int cbase = bn + wn + 2 * (lane & 3);
    #pragma unroll
    for (int fi = 0; fi < 2; fi++) {
        #pragma unroll
        for (int bj = 0; bj < 4; bj++) {
            int col = cbase + bj * 8;
            float bx = bias[col], by = bias[col + 1];
            int r0 = rbase + fi * 16;
            float2 v0 = {c[fi][bj][0] + bx, c[fi][bj][1] + by};
            float2 v1 = {c[fi][bj][2] + bx, c[fi][bj][3] + by};
            *(float2*)&g_gradx[(size_t)r0 * DIM + col] = v0;
            *(float2*)&g_gradx[(size_t)(r0 + 8) * DIM + col] = v1;
        }
    }
}

// ================ Gumbel: -log(-log u), fast-math-safe =================
__device__ __forceinline__ float gumbel_from_u(float u) {
    float nl = (u > 0.75f) ? (-log1pf(u - 1.0f)) : (-logf(u));
    return -logf(nl);
}

// ====== parallel top-2 of static keys = l0 + gumbel(u_t), per (b,t) ======
__global__ __launch_bounds__(256) void top2_kernel(
    const float* __restrict__ x, const float* __restrict__ unif,
    const int* __restrict__ radius)
{
    int t = blockIdx.x, b = blockIdx.y;
    if (t >= radius[b]) return;

    __shared__ __align__(16) float keys[DIM];
    __shared__ float rf[8];
    __shared__ int   ri[8];
    __shared__ float s_t1v; __shared__ int s_t1i;

    int tid = threadIdx.x, lane = tid & 31, wid = tid >> 5;
    const float* up = unif + ((size_t)t * BSZ + b) * DIM;
    const float* gx = g_gradx + (size_t)b * DIM;
    const float* xr = x + (size_t)b * DIM;

    float best = -3.0e38f; int bi = 0;
    #pragma unroll
    for (int i = 0; i < DIM / (NTHREADS * 4); i++) {
        int j = (tid << 2) + (i << 10);
        float4 u4 = *(const float4*)(up + j);
        float4 g4 = *(const float4*)(gx + j);
        float4 x4 = *(const float4*)(xr + j);
        float k0 = (1.f - 2.f * x4.x) * (0.5f * g4.x) + gumbel_from_u(u4.x);
        float k1 = (1.f - 2.f * x4.y) * (0.5f * g4.y) + gumbel_from_u(u4.y);
        float k2 = (1.f - 2.f * x4.z) * (0.5f * g4.z) + gumbel_from_u(u4.z);
        float k3 = (1.f - 2.f * x4.w) * (0.5f * g4.w) + gumbel_from_u(u4.w);
        *(float4*)&keys[j] = make_float4(k0, k1, k2, k3);
        if (k0 > best) { best = k0; bi = j; }
        if (k1 > best) { best = k1; bi = j + 1; }
        if (k2 > best) { best = k2; bi = j + 2; }
        if (k3 > best) { best = k3; bi = j + 3; }
    }
    #pragma unroll
    for (int o = 16; o; o >>= 1) {
        float ov = __shfl_down_sync(0xffffffffu, best, o);
        int   oi = __shfl_down_sync(0xffffffffu, bi, o);
        if (ov > best || (ov == best && oi < bi)) { best = ov; bi = oi; }
    }
    if (lane == 0) { rf[wid] = best; ri[wid] = bi; }
    __syncthreads();
    if (tid == 0) {
        float bv = rf[0]; int bbi = ri[0];
        #pragma unroll
        for (int w = 1; w < 8; w++)
            if (rf[w] > bv || (rf[w] == bv && ri[w] < bbi)) { bv = rf[w]; bbi = ri[w]; }
        s_t1v = bv; s_t1i = bbi;
        g_t1v[b * TMAX + t] = bv; g_t1i[b * TMAX + t] = bbi;
    }
    __syncthreads();
    int exc = s_t1i;
    best = -3.0e38f; bi = 0;
    #pragma unroll
    for (int i = 0; i < DIM / (NTHREADS * 4); i++) {
        int j = (tid << 2) + (i << 10);
        float4 k4 = *(const float4*)&keys[j];
        if (j + 0 != exc && k4.x > best) { best = k4.x; bi = j; }
        if (j + 1 != exc && k4.y > best) { best = k4.y; bi = j + 1; }
        if (j + 2 != exc && k4.z > best) { best = k4.z; bi = j + 2; }
        if (j + 3 != exc && k4.w > best) { best = k4.w; bi = j + 3; }
    }
    #pragma unroll
    for (int o = 16; o; o >>= 1) {
        float ov = __shfl_down_sync(0xffffffffu, best, o);
        int   oi = __shfl_down_sync(0xffffffffu, bi, o);
        if (ov > best || (ov == best && oi < bi)) { best = ov; bi = oi; }
    }
    if (lane == 0) { rf[wid] = best; ri[wid] = bi; }
    __syncthreads();
    if (tid == 0) {
        float bv = rf[0]; int bbi = ri[0];
        #pragma unroll
        for (int w = 1; w < 8; w++)
            if (rf[w] > bv || (rf[w] == bv && ri[w] < bbi)) { bv = rf[w]; bbi = ri[w]; }
        g_t2v[b * TMAX + t] = bv; g_t2i[b * TMAX + t] = bbi;
    }
}

// ============ serial scan using top-2 + corrected flipped keys ============
__global__ __launch_bounds__(256) void scan2_kernel(
    const float* __restrict__ x, const float* __restrict__ unif,
    const int* __restrict__ radius, const float* __restrict__ bias)
{
    __shared__ __align__(16) float al[DIM];
    __shared__ float rsum[8], rsum2[8];
    __shared__ float rf[8];
    __shared__ int   ri[8];
    __shared__ int   fset[TMAX];
    __shared__ float corrv[TMAX];
    __shared__ int   s_nf;
    __shared__ int   s_fb;

    int b = blockIdx.x;
    int tid = threadIdx.x, lane = tid & 31, wid = tid >> 5;

    const float* gx = g_gradx + (size_t)b * DIM;
    const float* xr = x + (size_t)b * DIM;

    float s_part = 0.f, sc_part = 0.f;
    for (int j = tid; j < DIM; j += NTHREADS) {
        float g  = gx[j];
        float xv = xr[j];
        float l  = (1.f - 2.f * xv) * (0.5f * g);
        al[j] = l;
        s_part  += expf(l);
        sc_part += xv * 0.5f * (g + bias[j]);
    }
    #pragma unroll
    for (int o = 16; o; o >>= 1) {
        s_part  += __shfl_down_sync(0xffffffffu, s_part, o);
        sc_part += __shfl_down_sync(0xffffffffu, sc_part, o);
    }
    if (lane == 0) { rsum[wid] = s_part; rsum2[wid] = sc_part; }
    if (tid == 0) s_nf = 0;
    __syncthreads();

    float S = 0.f, score = 0.f;
    if (tid == 0) {
        #pragma unroll
        for (int w = 0; w < 8; w++) { S += rsum[w]; score += rsum2[w]; }
    }

    int r = radius[b];
    float sum_sel = 0.f;

    for (int t = 0; t < r; t++) {
        __syncthreads();
        int nf = s_nf;
        if (tid < nf) {
            int i = fset[tid];
            float u = unif[((size_t)t * BSZ + b) * DIM + i];
            corrv[tid] = al[i] + gumbel_from_u(u);
        }
        __syncthreads();
        if (tid == 0) {
            int i1 = g_t1i[b * TMAX + t], i2 = g_t2i[b * TMAX + t];
            bool i1f = false, i2f = false;
            for (int f = 0; f < nf; f++) {
                if (fset[f] == i1) i1f = true;
                if (fset[f] == i2) i2f = true;
            }
            if (i1f && i2f) {
                s_fb = 1;
            } else {
                s_fb = 0;
                float candv; int candi;
                if (!i1f) { candv = g_t1v[b * TMAX + t]; candi = i1; }
                else      { candv = g_t2v[b * TMAX + t]; candi = i2; }
                float cbv = -3.0e38f; int cbi = 0x7fffffff; int cbf = -1;
                for (int f = 0; f < nf; f++) {
                    float v = corrv[f]; int i = fset[f];
                    if (v > cbv || (v == cbv && i < cbi)) { cbv = v; cbi = i; cbf = f; }
                }
                int istar; bool inF;
                if (nf > 0 && (cbv > candv || (cbv == candv && cbi < candi))) {
                    istar = cbi; inF = true;
                } else { istar = candi; inF = false; }
                float l = al[istar];
                sum_sel += l - logf(S);
                S += expf(-l) - expf(l);
                al[istar] = -l;
                if (inF) { fset[cbf] = fset[nf - 1]; s_nf = nf - 1; }
                else     { fset[nf] = istar; s_nf = nf + 1; }
                g_idxbuf[b * TMAX + t] = istar;
            }
        }
        __syncthreads();
        if (s_fb) {
            const float* up = unif + ((size_t)t * BSZ + b) * DIM;
            float best = -3.0e38f; int bi = 0;
            #pragma unroll
            for (int i = 0; i < DIM / (NTHREADS * 4); i++) {
                int j = (tid << 2) + (i << 10);
                float4 u4 = *(const float4*)(up + j);
                float4 a4 = *(const float4*)&al[j];
                float k0 = a4.x + gumbel_from_u(u4.x);
                float k1 = a4.y + gumbel_from_u(u4.y);
                float k2 = a4.z + gumbel_from_u(u4.z);
                float k3 = a4.w + gumbel_from_u(u4.w);
                if (k0 > best) { best = k0; bi = j; }
                if (k1 > best) { best = k1; bi = j + 1; }
                if (k2 > best) { best = k2; bi = j + 2; }
                if (k3 > best) { best = k3; bi = j + 3; }
            }
            #pragma unroll
            for (int o = 16; o; o >>= 1) {
                float ov = __shfl_down_sync(0xffffffffu, best, o);
                int   oi = __shfl_down_sync(0xffffffffu, bi, o);
                if (ov > best || (ov == best && oi < bi)) { best = ov; bi = oi; }
            }
            if (lane == 0) { rf[wid] = best; ri[wid] = bi; }
            __syncthreads();
            if (tid == 0) {
                float bv = rf[0]; int bbi = ri[0];
                #pragma unroll
                for (int w = 1; w < 8; w++)
                    if (rf[w] > bv || (rf[w] == bv && ri[w] < bbi)) { bv = rf[w]; bbi = ri[w]; }
                int nf2 = s_nf;
                float l = al[bbi];
                sum_sel += l - logf(S);
                S += expf(-l) - expf(l);
                al[bbi] = -l;
                int found = -1;
                for (int f = 0; f < nf2; f++) if (fset[f] == bbi) { found = f; break; }
                if (found >= 0) { fset[found] = fset[nf2 - 1]; s_nf = nf2 - 1; }
                else            { fset[nf2] = bbi; s_nf = nf2 + 1; }
                g_idxbuf[b * TMAX + t] = bbi;
            }
        }
    }
    __syncthreads();
    if (tid == 0) {
        g_logfwd[b] = sum_sel + score;
        int nf = s_nf;
        for (int a = 1; a < nf; a++) {
            int v = fset[a]; int c = a;
            while (c > 0 && fset[c - 1] > v) { fset[c] = fset[c - 1]; c--; }
            fset[c] = v;
        }
        g_nf[b] = nf;
        for (int f = 0; f < nf; f++) g_flipidx[b * TMAX + f] = fset[f];
    }
}

// ============ fused: sparse grad_y + backward + accept + output ============
__global__ __launch_bounds__(256) void bwd_fused(
    const float* __restrict__ x, const float* __restrict__ W,
    const float* __restrict__ bias, const float* __restrict__ uacc,
    const int* __restrict__ radius, float* __restrict__ out)
{
    __shared__ __align__(16) float gy[DIM];
    __shared__ __align__(16) float yb[DIM];
    __shared__ float rsum[8], rsum2[8];
    __shared__ int   fidx[TMAX + 1];
    __shared__ float fsgn[TMAX + 1];
    __shared__ float s_acc;

    int b = blockIdx.x;
    int tid = threadIdx.x;
    int lane = tid & 31, wid = tid >> 5;

    const float* xr  = x + (size_t)b * DIM;
    const float* gxr = g_gradx + (size_t)b * DIM;

    int n = g_nf[b];
    if (tid < n) {
        int i = g_flipidx[b * TMAX + tid];
        fidx[tid] = i;
        fsgn[tid] = 1.f - 2.f * xr[i];
    }
    __syncthreads();

    for (int j = tid; j < DIM; j += NTHREADS) {
        yb[j] = xr[j];
        float acc = gxr[j];
        for (int f = 0; f < n; f++)
            acc += fsgn[f] * W[(size_t)fidx[f] * DIM + j];
        gy[j] = acc;
    }
    __syncthreads();
    if (tid < n) yb[fidx[tid]] = 1.f - yb[fidx[tid]];
    __syncthreads();

    float s_part = 0.f, sc_part = 0.f;
    for (int j = tid; j < DIM; j += NTHREADS) {
        float g  = gy[j];
        float yv = yb[j];
        float l  = (1.f - 2.f * yv) * (0.5f * g);
        s_part  += expf(l);
        sc_part += yv * 0.5f * (g + bias[j]);
        gy[j] = l;
    }
    #pragma unroll
    for (int o = 16; o; o >>= 1) {
        s_part  += __shfl_down_sync(0xffffffffu, s_part, o);
        sc_part += __shfl_down_sync(0xffffffffu, sc_part, o);
    }
    if (lane == 0) { rsum[wid] = s_part; rsum2[wid] = sc_part; }
    __syncthreads();

    if (tid == 0) {
        float S = 0.f, score = 0.f;
        #pragma unroll
        for (int w = 0; w < 8; w++) { S += rsum[w]; score += rsum2[w]; }
        int r = radius[b];
        float sum_sel = 0.f;
        for (int t = r - 1; t >= 0; t--) {
            int i = g_idxbuf[b * TMAX + t];
            float l = gy[i];
            sum_sel += l - logf(S);
            S += expf(-l) - expf(l);
            gy[i] = -l;
        }
        float log_bwd = sum_sel + score;
        float ratio = expf(log_bwd - g_logfwd[b]);
        s_acc = (ratio >= uacc[b]) ? 1.0f : 0.0f;
    }
    __syncthreads();

    float a = s_acc;
    float* orow = out + (size_t)b * DIM;
    for (int j = tid << 2; j < DIM; j += NTHREADS * 4) {
        float4 yv4 = *(const float4*)&yb[j];
        float4 xv4 = *(const float4*)(xr + j);
        float4 o;
        o.x = (a != 0.f) ? yv4.x : xv4.x;
        o.y = (a != 0.f) ? yv4.y : xv4.y;
        o.z = (a != 0.f) ? yv4.z : xv4.z;
        o.w = (a != 0.f) ? yv4.w : xv4.w;
        *(float4*)(orow + j) = o;
    }
}

// =============================== launch ================================
extern "C" void kernel_launch(void* const* d_in, const int* in_sizes, int n_in,
                              void* d_out, int out_size)
{
    const float* x      = (const float*)d_in[0];
    const float* W      = (const float*)d_in[1];
    const float* bias   = (const float*)d_in[2];
    const float* unif   = (const float*)d_in[3];
    const float* uacc   = (const float*)d_in[4];
    const int*   radius = (const int*)d_in[5];
    float* out = (float*)d_out;

    cudaFuncSetAttribute(gemm_mma, cudaFuncAttributeMaxDynamicSharedMemorySize, SMEM_TOTAL);

    split_w_kernel<<<(DIM * DIM / 4) / 256, 256>>>(W);
    conv_x_kernel<<<(BSZ * DIM / 4) / 256, 256>>>(x);
    gemm_mma<<<dim3(DIM / BN, BSZ / BM), 256, SMEM_TOTAL>>>(bias);
    top2_kernel<<<dim3(TMAX, BSZ), 256>>>(x, unif, radius);
    scan2_kernel<<<BSZ, 256>>>(x, unif, radius, bias);
    bwd_fused<<<BSZ, 256>>>(x, W, bias, uacc, radius, out);
}